// round 1
// baseline (speedup 1.0000x reference)
#include <cuda_runtime.h>
#include <cstdint>

// Problem constants
#define P_TOTAL 8192      // 2*4*32*32 positions
#define DDIM    256       // embedding dim
#define E_TOTAL 8192      // codebook size
#define NSPLIT  4
#define E_PER_SPLIT (E_TOTAL / NSPLIT)   // 2048
#define BP 128            // positions per CTA tile
#define BE 128            // embeddings per chunk
#define BK 16             // k chunk

// Output layout (float32): z_q [2097152], loss [1], index [8192]
#define ZQ_ELEMS 2097152
#define LOSS_OFF 2097152
#define IDX_OFF  2097153

// Scratch (device globals; no allocation allowed)
__device__ float g_zl[P_TOTAL * DDIM];        // z transposed to [p][d]
__device__ float g_wsq[E_TOTAL];              // ||w_e||^2
__device__ float g_pminv[NSPLIT][P_TOTAL];    // partial min dist
__device__ int   g_pmini[NSPLIT][P_TOTAL];    // partial argmin
__device__ float g_blockloss[256];            // per-block loss partials

// ---------------- packed f32x2 helpers ----------------
__device__ __forceinline__ unsigned long long pack_dup(float x) {
    unsigned long long r;
    asm("mov.b64 %0, {%1, %1};" : "=l"(r) : "f"(x));
    return r;
}
__device__ __forceinline__ void ffma2(unsigned long long &acc,
                                      unsigned long long a,
                                      unsigned long long b) {
    asm("fma.rn.f32x2 %0, %1, %2, %0;" : "+l"(acc) : "l"(a), "l"(b));
}
__device__ __forceinline__ void unpack2(unsigned long long v, float &lo, float &hi) {
    asm("mov.b64 {%0, %1}, %2;" : "=f"(lo), "=f"(hi) : "l"(v));
}

// ---------------- Stage A1: transpose z [N,D,T,H,W] -> g_zl[p][d] ----------------
__global__ void vq_transpose(const float* __restrict__ z) {
    int idx = blockIdx.x * 256 + threadIdx.x;   // 0..2097151, coalesced read
    float v = z[idx];
    int n   = idx >> 20;            // /(256*4096)
    int rem = idx & 1048575;
    int d   = rem >> 12;            // /4096
    int thw = rem & 4095;
    g_zl[((n << 12) + thw) * DDIM + d] = v;
}

// ---------------- Stage A2: ||w_e||^2 (one warp per e) ----------------
__global__ void vq_wsq(const float* __restrict__ w) {
    int gwarp = (blockIdx.x * blockDim.x + threadIdx.x) >> 5;
    int lane  = threadIdx.x & 31;
    const float* row = w + (size_t)gwarp * DDIM;
    float4 a = *(const float4*)&row[lane * 4];
    float4 b = *(const float4*)&row[128 + lane * 4];
    float s = a.x*a.x + a.y*a.y + a.z*a.z + a.w*a.w
            + b.x*b.x + b.y*b.y + b.z*b.z + b.w*b.w;
    #pragma unroll
    for (int off = 16; off >= 1; off >>= 1)
        s += __shfl_down_sync(0xffffffffu, s, off);
    if (lane == 0) g_wsq[gwarp] = s;
}

// ---------------- Stage B: fused distance-GEMM + partial argmin ----------------
__global__ __launch_bounds__(256, 2)
void vq_gemm_argmin(const float* __restrict__ w) {
    __shared__ float zs[BK][BP + 4];   // k-major, padded
    __shared__ float ws[BK][BE + 4];

    const int t  = threadIdx.x;
    const int tx = t & 15;   // emb dim (16 threads)
    const int ty = t >> 4;   // pos dim (16 threads)
    const int p0 = blockIdx.x * BP;
    const int split = blockIdx.y;

    // loader mapping
    const int lrow = t >> 2;   // 0..63
    const int lc4  = t & 3;    // 0..3  (float4 column group)

    float bestv[8];
    int   besti[8];
    #pragma unroll
    for (int i = 0; i < 8; i++) { bestv[i] = __int_as_float(0x7f800000); besti[i] = 0; }

    for (int ch = 0; ch < E_PER_SPLIT / BE; ch++) {
        const int e0 = split * E_PER_SPLIT + ch * BE;

        unsigned long long acc[4][8];
        #pragma unroll
        for (int i = 0; i < 4; i++)
            #pragma unroll
            for (int j = 0; j < 8; j++) acc[i][j] = 0ULL;

        for (int k0 = 0; k0 < DDIM; k0 += BK) {
            __syncthreads();
            #pragma unroll
            for (int rr = 0; rr < 2; rr++) {
                const int r = lrow + rr * 64;
                float4 zv = *(const float4*)&g_zl[(p0 + r) * DDIM + k0 + lc4 * 4];
                zs[lc4*4+0][r] = zv.x; zs[lc4*4+1][r] = zv.y;
                zs[lc4*4+2][r] = zv.z; zs[lc4*4+3][r] = zv.w;
                float4 wv = *(const float4*)&w[(size_t)(e0 + r) * DDIM + k0 + lc4 * 4];
                ws[lc4*4+0][r] = wv.x; ws[lc4*4+1][r] = wv.y;
                ws[lc4*4+2][r] = wv.z; ws[lc4*4+3][r] = wv.w;
            }
            __syncthreads();

            #pragma unroll
            for (int kk = 0; kk < BK; kk++) {
                ulonglong2 za = *(const ulonglong2*)&zs[kk][ty * 8];
                ulonglong2 zb = *(const ulonglong2*)&zs[kk][ty * 8 + 4];
                float4 wa = *(const float4*)&ws[kk][tx * 8];
                float4 wb = *(const float4*)&ws[kk][tx * 8 + 4];
                float wv[8] = {wa.x, wa.y, wa.z, wa.w, wb.x, wb.y, wb.z, wb.w};
                #pragma unroll
                for (int j = 0; j < 8; j++) {
                    unsigned long long wp = pack_dup(wv[j]);
                    ffma2(acc[0][j], za.x, wp);
                    ffma2(acc[1][j], za.y, wp);
                    ffma2(acc[2][j], zb.x, wp);
                    ffma2(acc[3][j], zb.y, wp);
                }
            }
        }

        // epilogue: d = ||w||^2 - 2*dot ; running argmin (e ascending)
        #pragma unroll
        for (int j = 0; j < 8; j++) {
            const int e = e0 + tx * 8 + j;
            const float wq = g_wsq[e];
            #pragma unroll
            for (int i = 0; i < 4; i++) {
                float lo, hi;
                unpack2(acc[i][j], lo, hi);
                float d0 = wq - 2.0f * lo;
                float d1 = wq - 2.0f * hi;
                if (d0 < bestv[2*i])   { bestv[2*i]   = d0; besti[2*i]   = e; }
                if (d1 < bestv[2*i+1]) { bestv[2*i+1] = d1; besti[2*i+1] = e; }
            }
        }
    }

    // reduce across the 16 emb-threads (tx) sharing each position row
    #pragma unroll
    for (int i = 0; i < 8; i++) {
        float v = bestv[i];
        int  id = besti[i];
        #pragma unroll
        for (int off = 8; off >= 1; off >>= 1) {
            float ov = __shfl_xor_sync(0xffffffffu, v, off);
            int   oi = __shfl_xor_sync(0xffffffffu, id, off);
            if (ov < v || (ov == v && oi < id)) { v = ov; id = oi; }
        }
        if (tx == 0) {
            int p = p0 + ty * 8 + i;
            g_pminv[split][p] = v;
            g_pmini[split][p] = id;
        }
    }
}

// ---------------- Stage C: combine splits, gather z_q, scatter, loss partials ----
__global__ void vq_gather(const float* __restrict__ w, float* __restrict__ out) {
    __shared__ float lsum[256];
    const int t = threadIdx.x;
    const int p = blockIdx.x * 32 + (t >> 3);   // 32 positions per block
    const int j = t & 7;                        // 8 threads per position

    float bv = g_pminv[0][p];
    int   bi = g_pmini[0][p];
    #pragma unroll
    for (int s = 1; s < NSPLIT; s++) {
        float v = g_pminv[s][p];
        int  id = g_pmini[s][p];
        if (v < bv) { bv = v; bi = id; }   // ties keep lower split == lower index
    }

    const int n   = p >> 12;
    const int thw = p & 4095;
    const int obase = n * 1048576 + thw;

    float acc = 0.0f;
    #pragma unroll
    for (int q = 0; q < 8; q++) {
        const int d = j * 32 + q * 4;
        float4 wv = *(const float4*)&w[(size_t)bi * DDIM + d];
        float4 zv = *(const float4*)&g_zl[(size_t)p * DDIM + d];
        out[obase + (d + 0) * 4096] = wv.x;
        out[obase + (d + 1) * 4096] = wv.y;
        out[obase + (d + 2) * 4096] = wv.z;
        out[obase + (d + 3) * 4096] = wv.w;
        float dx = wv.x - zv.x, dy = wv.y - zv.y;
        float dz = wv.z - zv.z, dw = wv.w - zv.w;
        acc += dx*dx + dy*dy + dz*dz + dw*dw;
    }
    if (j == 0) out[IDX_OFF + p] = (float)bi;

    lsum[t] = acc;
    __syncthreads();
    #pragma unroll
    for (int s = 128; s > 0; s >>= 1) {
        if (t < s) lsum[t] += lsum[t + s];
        __syncthreads();
    }
    if (t == 0) g_blockloss[blockIdx.x] = lsum[0];
}

// ---------------- Stage D: final deterministic loss reduction ----------------
__global__ void vq_loss(float* __restrict__ out) {
    __shared__ float s[256];
    const int t = threadIdx.x;
    s[t] = g_blockloss[t];
    __syncthreads();
    #pragma unroll
    for (int k = 128; k > 0; k >>= 1) {
        if (t < k) s[t] += s[t + k];
        __syncthreads();
    }
    if (t == 0) out[LOSS_OFF] = 1.25f * s[0] / (float)ZQ_ELEMS;
}

// ---------------- launch ----------------
extern "C" void kernel_launch(void* const* d_in, const int* in_sizes, int n_in,
                              void* d_out, int out_size) {
    const float* z = (const float*)d_in[0];        // [2,256,4,32,32]
    const float* w = (const float*)d_in[1];        // [8192,256]
    float* out = (float*)d_out;

    vq_transpose<<<8192, 256>>>(z);
    vq_wsq<<<1024, 256>>>(w);                      // 8192 warps
    dim3 grid(P_TOTAL / BP, NSPLIT);               // 64 x 4 = 256 CTAs
    vq_gemm_argmin<<<grid, 256>>>(w);
    vq_gather<<<P_TOTAL / 32, 256>>>(w, out);      // 256 blocks
    vq_loss<<<1, 256>>>(out);
}

// round 3
// speedup vs baseline: 1.1480x; 1.1480x over previous
#include <cuda_runtime.h>
#include <cstdint>

// ---------------- problem constants ----------------
#define P_TOTAL 8192      // 2*4*32*32 positions
#define DDIM    256
#define E_TOTAL 8192
#define NSPLIT  2
#define E_PER   (E_TOTAL / NSPLIT)     // 4096

#define ZQ_ELEMS 2097152
#define LOSS_OFF 2097152
#define IDX_OFF  2097153

// ---------------- GEMM tiling ----------------
#define BM 128
#define BN 256
#define BK 32
#define KSTEPS 24                      // 3 passes x 8 k-steps (virtual K = 768)
#define NCHUNK (E_PER / BN)            // 16
#define TSTRIDE 36                     // floats per smem row (conflict-free)
#define AS_BYTES (BM * TSTRIDE * 4)    // 18432
#define BS_BYTES (BN * TSTRIDE * 4)    // 36864
#define BUF_BYTES (AS_BYTES + BS_BYTES)        // 55296
#define SMEM_TOTAL (2 * BUF_BYTES + 1024)      // 111616 + wsq

// ---------------- scratch (device globals) ----------------
__device__ __align__(256) float g_zhi[P_TOTAL * DDIM];
__device__ __align__(256) float g_zlo[P_TOTAL * DDIM];
__device__ __align__(256) float g_whi[E_TOTAL * DDIM];
__device__ __align__(256) float g_wlo[E_TOTAL * DDIM];
__device__ __align__(256) float g_wsq[E_TOTAL];
__device__ float g_pminv[NSPLIT][P_TOTAL];
__device__ int   g_pmini[NSPLIT][P_TOTAL];
__device__ float g_blockloss[256];

// ---------------- helpers ----------------
__device__ __forceinline__ uint32_t smem_u32(const void* p) {
    uint32_t a;
    asm("{ .reg .u64 t; cvta.to.shared.u64 t, %1; cvt.u32.u64 %0, t; }" : "=r"(a) : "l"(p));
    return a;
}
#define CP16(sa, ga) \
    asm volatile("cp.async.cg.shared.global [%0], [%1], 16;" :: "r"((uint32_t)(sa)), "l"(ga))
#define CP_COMMIT() asm volatile("cp.async.commit_group;" ::: "memory")
#define CP_WAIT1()  asm volatile("cp.async.wait_group 1;" ::: "memory")
#define CP_WAIT0()  asm volatile("cp.async.wait_group 0;" ::: "memory")

__device__ __forceinline__ float tf32r(float x) {
    uint32_t r;
    asm("cvt.rna.tf32.f32 %0, %1;" : "=r"(r) : "f"(x));
    return __uint_as_float(r);
}
__device__ __forceinline__ uint32_t lds_u32(uint32_t addr) {
    uint32_t v;
    asm volatile("ld.shared.b32 %0, [%1];" : "=r"(v) : "r"(addr));
    return v;
}
__device__ __forceinline__ void mma_tf32(float& c0, float& c1, float& c2, float& c3,
                                         uint32_t a0, uint32_t a1, uint32_t a2, uint32_t a3,
                                         uint32_t b0, uint32_t b1) {
    asm volatile("mma.sync.aligned.m16n8k8.row.col.f32.tf32.tf32.f32 "
                 "{%0,%1,%2,%3}, {%4,%5,%6,%7}, {%8,%9}, {%0,%1,%2,%3};"
                 : "+f"(c0), "+f"(c1), "+f"(c2), "+f"(c3)
                 : "r"(a0), "r"(a1), "r"(a2), "r"(a3), "r"(b0), "r"(b1));
}

// ---------------- Stage A1: z -> (z_hi, z_lo) transposed to [p][d] ----------------
__global__ void vq_prep_z(const float* __restrict__ z) {
    int idx = blockIdx.x * 256 + threadIdx.x;
    float v = z[idx];
    int n = idx >> 20, rem = idx & 1048575;
    int d = rem >> 12, thw = rem & 4095;
    int o = ((n << 12) + thw) * DDIM + d;
    float hi = tf32r(v);
    g_zhi[o] = hi;
    g_zlo[o] = tf32r(v - hi);
}

// ---------------- Stage A2: w -> (w_hi, w_lo) ----------------
__global__ void vq_prep_w(const float* __restrict__ w) {
    int idx = blockIdx.x * 256 + threadIdx.x;
    float v = w[idx];
    float hi = tf32r(v);
    g_whi[idx] = hi;
    g_wlo[idx] = tf32r(v - hi);
}

// ---------------- Stage A3: ||w_e||^2 (fp32 exact) ----------------
__global__ void vq_wsq(const float* __restrict__ w) {
    int gwarp = (blockIdx.x * blockDim.x + threadIdx.x) >> 5;
    int lane = threadIdx.x & 31;
    const float* row = w + (size_t)gwarp * DDIM;
    float4 a = *(const float4*)&row[lane * 4];
    float4 b = *(const float4*)&row[128 + lane * 4];
    float s = a.x*a.x + a.y*a.y + a.z*a.z + a.w*a.w
            + b.x*b.x + b.y*b.y + b.z*b.z + b.w*b.w;
    #pragma unroll
    for (int off = 16; off >= 1; off >>= 1)
        s += __shfl_down_sync(0xffffffffu, s, off);
    if (lane == 0) g_wsq[gwarp] = s;
}

// ---------------- Stage B: mma.sync 3xTF32 distance GEMM + argmin ----------------
__global__ __launch_bounds__(256, 1)
void vq_mma() {
    extern __shared__ float sm[];
    float* wsq_s = sm + 2 * BUF_BYTES / 4;
    const uint32_t sb = smem_u32(sm);

    const int t = threadIdx.x;
    const int lane = t & 31, wid = t >> 5;
    const int warpM = wid >> 2;          // 0..1
    const int warpN = wid & 3;           // 0..3
    const int g = lane >> 2;             // 0..7 (group)
    const int tg = lane & 3;             // 0..3 (thread-in-group)
    const int p0 = blockIdx.x * BM;
    const int split = blockIdx.y;

    float bestv[4][2];
    int   besti[4][2];
    #pragma unroll
    for (int mi = 0; mi < 4; mi++)
        #pragma unroll
        for (int h = 0; h < 2; h++) { bestv[mi][h] = __int_as_float(0x7f800000); besti[mi][h] = 0; }

    for (int ch = 0; ch < NCHUNK; ch++) {
        const int e0 = split * E_PER + ch * BN;
        __syncthreads();                    // previous epilogue done before wsq_s reuse
        wsq_s[t] = g_wsq[e0 + t];

        float acc[4][8][4];
        #pragma unroll
        for (int mi = 0; mi < 4; mi++)
            #pragma unroll
            for (int ni = 0; ni < 8; ni++)
                #pragma unroll
                for (int q = 0; q < 4; q++) acc[mi][ni][q] = 0.0f;

        // ---- tile loader (s = virtual k-step) ----
        auto load_tiles = [&](int s) {
            const int pass = s >> 3;
            const int k0 = (s & 7) * BK;
            const float* Ab = (pass == 1) ? g_zlo : g_zhi;
            const float* Bb = (pass == 2) ? g_wlo : g_whi;
            const uint32_t base = sb + (uint32_t)(s & 1) * BUF_BYTES;
            const float* Asrc = Ab + (size_t)p0 * DDIM + k0;
            #pragma unroll
            for (int i = 0; i < 4; i++) {
                int op = t + i * 256;
                int row = op >> 3, qc = op & 7;
                CP16(base + (uint32_t)(row * TSTRIDE + qc * 4) * 4,
                     Asrc + (size_t)row * DDIM + qc * 4);
            }
            const float* Bsrc = Bb + (size_t)e0 * DDIM + k0;
            #pragma unroll
            for (int i = 0; i < 8; i++) {
                int op = t + i * 256;
                int row = op >> 3, qc = op & 7;
                CP16(base + AS_BYTES + (uint32_t)(row * TSTRIDE + qc * 4) * 4,
                     Bsrc + (size_t)row * DDIM + qc * 4);
            }
            CP_COMMIT();
        };

        load_tiles(0);
        #pragma unroll 1
        for (int s = 0; s < KSTEPS; s++) {
            if (s + 1 < KSTEPS) { load_tiles(s + 1); CP_WAIT1(); }
            else                { CP_WAIT0(); }
            __syncthreads();

            const uint32_t As = sb + (uint32_t)(s & 1) * BUF_BYTES;
            const uint32_t Bs = As + AS_BYTES;
            #pragma unroll
            for (int k8 = 0; k8 < 4; k8++) {
                const int kk = k8 * 8 + tg;
                uint32_t a[4][4];
                #pragma unroll
                for (int mi = 0; mi < 4; mi++) {
                    const int r0 = warpM * 64 + mi * 16 + g;
                    a[mi][0] = lds_u32(As + (uint32_t)(r0 * TSTRIDE + kk) * 4);
                    a[mi][1] = lds_u32(As + (uint32_t)((r0 + 8) * TSTRIDE + kk) * 4);
                    a[mi][2] = lds_u32(As + (uint32_t)(r0 * TSTRIDE + kk + 4) * 4);
                    a[mi][3] = lds_u32(As + (uint32_t)((r0 + 8) * TSTRIDE + kk + 4) * 4);
                }
                uint32_t b[8][2];
                #pragma unroll
                for (int ni = 0; ni < 8; ni++) {
                    const int col = warpN * 64 + ni * 8 + g;
                    b[ni][0] = lds_u32(Bs + (uint32_t)(col * TSTRIDE + kk) * 4);
                    b[ni][1] = lds_u32(Bs + (uint32_t)(col * TSTRIDE + kk + 4) * 4);
                }
                #pragma unroll
                for (int mi = 0; mi < 4; mi++)
                    #pragma unroll
                    for (int ni = 0; ni < 8; ni++)
                        mma_tf32(acc[mi][ni][0], acc[mi][ni][1], acc[mi][ni][2], acc[mi][ni][3],
                                 a[mi][0], a[mi][1], a[mi][2], a[mi][3],
                                 b[ni][0], b[ni][1]);
            }
            __syncthreads();
        }

        // ---- chunk epilogue: d = ||w||^2 - 2S, running argmin ----
        #pragma unroll
        for (int mi = 0; mi < 4; mi++) {
            #pragma unroll
            for (int ni = 0; ni < 8; ni++) {
                const int cl = warpN * 64 + ni * 8 + tg * 2;
                const float w0 = wsq_s[cl], w1 = wsq_s[cl + 1];
                #pragma unroll
                for (int h = 0; h < 2; h++) {
                    float d0 = w0 - 2.0f * acc[mi][ni][h * 2 + 0];
                    float d1 = w1 - 2.0f * acc[mi][ni][h * 2 + 1];
                    if (d0 < bestv[mi][h]) { bestv[mi][h] = d0; besti[mi][h] = e0 + cl; }
                    if (d1 < bestv[mi][h]) { bestv[mi][h] = d1; besti[mi][h] = e0 + cl + 1; }
                }
            }
        }
    }

    // ---- final cross-thread argmin reduce (smem overlay on tile buffers) ----
    __syncthreads();
    float* redv = sm;                       // 128*16 floats = 8KB
    int*   redi = (int*)(sm + 2048);        // next 8KB
    #pragma unroll
    for (int mi = 0; mi < 4; mi++)
        #pragma unroll
        for (int h = 0; h < 2; h++) {
            int r = warpM * 64 + mi * 16 + h * 8 + g;
            int slot = warpN * 4 + tg;
            redv[r * 16 + slot] = bestv[mi][h];
            redi[r * 16 + slot] = besti[mi][h];
        }
    __syncthreads();
    if (t < BM) {
        float v = redv[t * 16];
        int   i = redi[t * 16];
        #pragma unroll
        for (int s = 1; s < 16; s++) {
            float ov = redv[t * 16 + s];
            int   oi = redi[t * 16 + s];
            if (ov < v || (ov == v && oi < i)) { v = ov; i = oi; }
        }
        g_pminv[split][p0 + t] = v;
        g_pmini[split][p0 + t] = i;
    }
}

// ---------------- Stage C: combine splits, gather z_q, loss partials ----------------
__global__ void vq_gather(const float* __restrict__ w, float* __restrict__ out) {
    __shared__ float lsum[256];
    const int t = threadIdx.x;
    const int p = blockIdx.x * 32 + (t >> 3);
    const int j = t & 7;

    float bv = g_pminv[0][p];
    int bi = g_pmini[0][p];
    #pragma unroll
    for (int s = 1; s < NSPLIT; s++) {
        float v = g_pminv[s][p];
        int id = g_pmini[s][p];
        if (v < bv || (v == bv && id < bi)) { bv = v; bi = id; }
    }

    const int n = p >> 12;
    const int thw = p & 4095;
    const int obase = n * 1048576 + thw;

    float acc = 0.0f;
    #pragma unroll
    for (int q = 0; q < 8; q++) {
        const int d = j * 32 + q * 4;
        float4 wv = *(const float4*)&w[(size_t)bi * DDIM + d];
        float4 zh = *(const float4*)&g_zhi[(size_t)p * DDIM + d];
        float4 zl = *(const float4*)&g_zlo[(size_t)p * DDIM + d];
        out[obase + (d + 0) * 4096] = wv.x;
        out[obase + (d + 1) * 4096] = wv.y;
        out[obase + (d + 2) * 4096] = wv.z;
        out[obase + (d + 3) * 4096] = wv.w;
        float dx = wv.x - (zh.x + zl.x), dy = wv.y - (zh.y + zl.y);
        float dz = wv.z - (zh.z + zl.z), dw = wv.w - (zh.w + zl.w);
        acc += dx*dx + dy*dy + dz*dz + dw*dw;
    }
    if (j == 0) out[IDX_OFF + p] = (float)bi;

    lsum[t] = acc;
    __syncthreads();
    #pragma unroll
    for (int s = 128; s > 0; s >>= 1) {
        if (t < s) lsum[t] += lsum[t + s];
        __syncthreads();
    }
    if (t == 0) g_blockloss[blockIdx.x] = lsum[0];
}

// ---------------- Stage D: deterministic loss reduction ----------------
__global__ void vq_loss(float* __restrict__ out) {
    __shared__ float s[256];
    const int t = threadIdx.x;
    s[t] = g_blockloss[t];
    __syncthreads();
    #pragma unroll
    for (int k = 128; k > 0; k >>= 1) {
        if (t < k) s[t] += s[t + k];
        __syncthreads();
    }
    if (t == 0) out[LOSS_OFF] = 1.25f * s[0] / (float)ZQ_ELEMS;
}

// ---------------- launch ----------------
extern "C" void kernel_launch(void* const* d_in, const int* in_sizes, int n_in,
                              void* d_out, int out_size) {
    const float* z = (const float*)d_in[0];
    const float* w = (const float*)d_in[1];
    float* out = (float*)d_out;

    cudaFuncSetAttribute(vq_mma, cudaFuncAttributeMaxDynamicSharedMemorySize, SMEM_TOTAL);

    vq_prep_z<<<8192, 256>>>(z);
    vq_prep_w<<<8192, 256>>>(w);
    vq_wsq<<<1024, 256>>>(w);
    dim3 grid(P_TOTAL / BM, NSPLIT);       // 64 x 2 = 128 CTAs
    vq_mma<<<grid, 256, SMEM_TOTAL>>>();
    vq_gather<<<P_TOTAL / 32, 256>>>(w, out);
    vq_loss<<<1, 256>>>(out);
}

// round 4
// speedup vs baseline: 1.1807x; 1.0285x over previous
#include <cuda_runtime.h>
#include <cstdint>

// ---------------- problem constants ----------------
#define P_TOTAL 8192
#define DDIM    256
#define E_TOTAL 8192
#define NSPLIT  2
#define E_PER   (E_TOTAL / NSPLIT)     // 4096

#define ZQ_ELEMS 2097152
#define LOSS_OFF 2097152
#define IDX_OFF  2097153

// ---------------- GEMM tiling ----------------
#define BM 128
#define BN 256
#define BK 32
#define NCHUNK (E_PER / BN)            // 16
#define NSTEPS (NCHUNK * 16)           // 256: 16 steps/chunk (8 dual + 8 single)
#define TS 36                          // words per smem row
#define ROWB (TS * 4)                  // 144 bytes per row
#define A_BYTES (BM * ROWB)            // 18432
#define B_BYTES (BN * ROWB)            // 36864
#define STAGE_BYTES (2 * A_BYTES + B_BYTES)   // 73728
#define SMEM_TOTAL (3 * STAGE_BYTES)          // 221184

// ---------------- scratch ----------------
__device__ __align__(256) float g_zhi[P_TOTAL * DDIM];   // k-permuted
__device__ __align__(256) float g_zlo[P_TOTAL * DDIM];   // k-permuted
__device__ __align__(256) float g_zl [P_TOTAL * DDIM];   // plain [p][d]
__device__ __align__(256) float g_whi[E_TOTAL * DDIM];   // k-permuted
__device__ __align__(256) float g_wlo[E_TOTAL * DDIM];   // k-permuted
__device__ __align__(256) float g_wsq[E_TOTAL];
__device__ float g_pminv[NSPLIT][P_TOTAL];
__device__ int   g_pmini[NSPLIT][P_TOTAL];
__device__ float g_blockloss[256];

// ---------------- helpers ----------------
__device__ __forceinline__ uint32_t smem_u32(const void* p) {
    uint32_t a;
    asm("{ .reg .u64 t; cvta.to.shared.u64 t, %1; cvt.u32.u64 %0, t; }" : "=r"(a) : "l"(p));
    return a;
}
#define CP16(sa, ga) \
    asm volatile("cp.async.cg.shared.global [%0], [%1], 16;" :: "r"((uint32_t)(sa)), "l"(ga))
#define CP_COMMIT() asm volatile("cp.async.commit_group;" ::: "memory")
#define CP_WAIT1()  asm volatile("cp.async.wait_group 1;" ::: "memory")
#define CP_WAIT0()  asm volatile("cp.async.wait_group 0;" ::: "memory")

__device__ __forceinline__ float tf32r(float x) {
    uint32_t r;
    asm("cvt.rna.tf32.f32 %0, %1;" : "=r"(r) : "f"(x));
    return __uint_as_float(r);
}
__device__ __forceinline__ uint2 lds_u64(uint32_t addr) {
    uint2 v;
    asm volatile("ld.shared.v2.b32 {%0,%1}, [%2];" : "=r"(v.x), "=r"(v.y) : "r"(addr));
    return v;
}
__device__ __forceinline__ void mma_tf32(float& c0, float& c1, float& c2, float& c3,
                                         uint32_t a0, uint32_t a1, uint32_t a2, uint32_t a3,
                                         uint32_t b0, uint32_t b1) {
    asm volatile("mma.sync.aligned.m16n8k8.row.col.f32.tf32.tf32.f32 "
                 "{%0,%1,%2,%3}, {%4,%5,%6,%7}, {%8,%9}, {%0,%1,%2,%3};"
                 : "+f"(c0), "+f"(c1), "+f"(c2), "+f"(c3)
                 : "r"(a0), "r"(a1), "r"(a2), "r"(a3), "r"(b0), "r"(b1));
}
// k-permutation: makes (k, k+4) adjacent within each 8-block
__device__ __forceinline__ int dperm(int d) {
    return ((d >> 3) << 3) + ((d & 3) << 1) + ((d >> 2) & 1);
}

// ---------------- Stage A1: z -> (z_hi, z_lo) permuted + plain z_l ----------------
__global__ void vq_prep_z(const float* __restrict__ z) {
    int idx = blockIdx.x * 256 + threadIdx.x;
    float v = z[idx];
    int n = idx >> 20, rem = idx & 1048575;
    int d = rem >> 12, thw = rem & 4095;
    int p = (n << 12) + thw;
    float hi = tf32r(v);
    int op = p * DDIM + dperm(d);
    g_zhi[op] = hi;
    g_zlo[op] = tf32r(v - hi);
    g_zl[p * DDIM + d] = v;
}

// ---------------- Stage A2: w -> (w_hi, w_lo) permuted ----------------
__global__ void vq_prep_w(const float* __restrict__ w) {
    int idx = blockIdx.x * 256 + threadIdx.x;
    float v = w[idx];
    int e = idx >> 8, d = idx & 255;
    float hi = tf32r(v);
    int op = e * DDIM + dperm(d);
    g_whi[op] = hi;
    g_wlo[op] = tf32r(v - hi);
}

// ---------------- Stage A3: ||w_e||^2 ----------------
__global__ void vq_wsq(const float* __restrict__ w) {
    int gwarp = (blockIdx.x * blockDim.x + threadIdx.x) >> 5;
    int lane = threadIdx.x & 31;
    const float* row = w + (size_t)gwarp * DDIM;
    float4 a = *(const float4*)&row[lane * 4];
    float4 b = *(const float4*)&row[128 + lane * 4];
    float s = a.x*a.x + a.y*a.y + a.z*a.z + a.w*a.w
            + b.x*b.x + b.y*b.y + b.z*b.z + b.w*b.w;
    #pragma unroll
    for (int off = 16; off >= 1; off >>= 1)
        s += __shfl_down_sync(0xffffffffu, s, off);
    if (lane == 0) g_wsq[gwarp] = s;
}

// ---------------- Stage B: 3xTF32 distance GEMM + argmin ----------------
__global__ __launch_bounds__(256, 1)
void vq_mma() {
    extern __shared__ float sm[];
    const uint32_t sb = smem_u32(sm);

    const int t = threadIdx.x;
    const int lane = t & 31, wid = t >> 5;
    const int warpM = wid >> 2;          // 0..1
    const int warpN = wid & 3;           // 0..3
    const int g = lane >> 2;             // 0..7
    const int tg = lane & 3;             // 0..3
    const int p0 = blockIdx.x * BM;
    const int split = blockIdx.y;
    const uint32_t koff_tg = tg * 8;     // (tg*2 words)*4 bytes

    float bestv[4][2];
    int   besti[4][2];
    #pragma unroll
    for (int mi = 0; mi < 4; mi++)
        #pragma unroll
        for (int h = 0; h < 2; h++) { bestv[mi][h] = __int_as_float(0x7f800000); besti[mi][h] = 0; }

    float acc[4][8][4];

    // ---- loader: step L -> stage L%3 ----
    auto issue_load = [&](int L) {
        const int ch = L >> 4, sl = L & 15;
        const int ph = sl >> 3;          // 0: dual-A vs B_hi, 1: A_hi vs B_lo
        const int k0 = (sl & 7) * BK;
        const uint32_t base = sb + (uint32_t)(L % 3) * STAGE_BYTES;
        const size_t aoff = (size_t)p0 * DDIM + k0;
        #pragma unroll
        for (int i = 0; i < 4; i++) {
            int op = t + i * 256;
            int row = op >> 3, qc = op & 7;
            CP16(base + (uint32_t)(row * ROWB + qc * 16),
                 g_zhi + aoff + (size_t)row * DDIM + qc * 4);
        }
        if (ph == 0) {
            #pragma unroll
            for (int i = 0; i < 4; i++) {
                int op = t + i * 256;
                int row = op >> 3, qc = op & 7;
                CP16(base + A_BYTES + (uint32_t)(row * ROWB + qc * 16),
                     g_zlo + aoff + (size_t)row * DDIM + qc * 4);
            }
        }
        const float* Bsrc = (ph == 0 ? g_whi : g_wlo)
                          + (size_t)(split * E_PER + ch * BN) * DDIM + k0;
        #pragma unroll
        for (int i = 0; i < 8; i++) {
            int op = t + i * 256;
            int row = op >> 3, qc = op & 7;
            CP16(base + 2 * A_BYTES + (uint32_t)(row * ROWB + qc * 16),
                 Bsrc + (size_t)row * DDIM + qc * 4);
        }
        CP_COMMIT();
    };

    issue_load(0);
    issue_load(1);

    #pragma unroll 1
    for (int S = 0; S < NSTEPS; S++) {
        if (S < NSTEPS - 1) CP_WAIT1(); else CP_WAIT0();
        __syncthreads();
        if (S + 2 < NSTEPS) issue_load(S + 2);

        const int s16 = S & 15;
        const int ph = s16 >> 3;
        if (s16 == 0) {
            #pragma unroll
            for (int mi = 0; mi < 4; mi++)
                #pragma unroll
                for (int ni = 0; ni < 8; ni++)
                    #pragma unroll
                    for (int q = 0; q < 4; q++) acc[mi][ni][q] = 0.0f;
        }

        const uint32_t base = sb + (uint32_t)(S % 3) * STAGE_BYTES;
        const uint32_t As1 = base;
        const uint32_t As2 = base + A_BYTES;
        const uint32_t Bs  = base + 2 * A_BYTES;

        #pragma unroll
        for (int k8 = 0; k8 < 4; k8++) {
            const uint32_t ko = k8 * 32 + koff_tg;   // (k8*8 + tg*2) words in bytes
            uint2 b[8];
            #pragma unroll
            for (int ni = 0; ni < 8; ni++)
                b[ni] = lds_u64(Bs + (uint32_t)((warpN * 64 + ni * 8 + g) * ROWB) + ko);
            #pragma unroll
            for (int mi = 0; mi < 4; mi++) {
                const uint32_t ra = (uint32_t)((warpM * 64 + mi * 16 + g) * ROWB) + ko;
                uint2 aA = lds_u64(As1 + ra);
                uint2 aB = lds_u64(As1 + ra + 8 * ROWB);
                #pragma unroll
                for (int ni = 0; ni < 8; ni++)
                    mma_tf32(acc[mi][ni][0], acc[mi][ni][1], acc[mi][ni][2], acc[mi][ni][3],
                             aA.x, aB.x, aA.y, aB.y, b[ni].x, b[ni].y);
            }
            if (ph == 0) {
                #pragma unroll
                for (int mi = 0; mi < 4; mi++) {
                    const uint32_t ra = (uint32_t)((warpM * 64 + mi * 16 + g) * ROWB) + ko;
                    uint2 aA = lds_u64(As2 + ra);
                    uint2 aB = lds_u64(As2 + ra + 8 * ROWB);
                    #pragma unroll
                    for (int ni = 0; ni < 8; ni++)
                        mma_tf32(acc[mi][ni][0], acc[mi][ni][1], acc[mi][ni][2], acc[mi][ni][3],
                                 aA.x, aB.x, aA.y, aB.y, b[ni].x, b[ni].y);
                }
            }
        }

        if (s16 == 15) {   // chunk epilogue: d = ||w||^2 - 2S, running argmin
            const int e0 = split * E_PER + (S >> 4) * BN;
            #pragma unroll
            for (int ni = 0; ni < 8; ni++) {
                const int cl = warpN * 64 + ni * 8 + tg * 2;
                const float2 wq = *(const float2*)&g_wsq[e0 + cl];
                #pragma unroll
                for (int mi = 0; mi < 4; mi++) {
                    #pragma unroll
                    for (int h = 0; h < 2; h++) {
                        float d0 = wq.x - 2.0f * acc[mi][ni][h * 2 + 0];
                        float d1 = wq.y - 2.0f * acc[mi][ni][h * 2 + 1];
                        if (d0 < bestv[mi][h]) { bestv[mi][h] = d0; besti[mi][h] = e0 + cl; }
                        if (d1 < bestv[mi][h]) { bestv[mi][h] = d1; besti[mi][h] = e0 + cl + 1; }
                    }
                }
            }
        }
    }

    // ---- final cross-thread argmin reduce (overlay on tile smem) ----
    __syncthreads();
    float* redv = sm;
    int*   redi = (int*)(sm + 2048);
    #pragma unroll
    for (int mi = 0; mi < 4; mi++)
        #pragma unroll
        for (int h = 0; h < 2; h++) {
            int r = warpM * 64 + mi * 16 + h * 8 + g;
            int slot = warpN * 4 + tg;
            redv[r * 16 + slot] = bestv[mi][h];
            redi[r * 16 + slot] = besti[mi][h];
        }
    __syncthreads();
    if (t < BM) {
        float v = redv[t * 16];
        int   i = redi[t * 16];
        #pragma unroll
        for (int s = 1; s < 16; s++) {
            float ov = redv[t * 16 + s];
            int   oi = redi[t * 16 + s];
            if (ov < v || (ov == v && oi < i)) { v = ov; i = oi; }
        }
        g_pminv[split][p0 + t] = v;
        g_pmini[split][p0 + t] = i;
    }
}

// ---------------- Stage C: combine splits, gather z_q, loss partials ----------------
__global__ void vq_gather(const float* __restrict__ w, float* __restrict__ out) {
    __shared__ float lsum[256];
    const int t = threadIdx.x;
    const int p = blockIdx.x * 32 + (t >> 3);
    const int j = t & 7;

    float bv = g_pminv[0][p];
    int bi = g_pmini[0][p];
    #pragma unroll
    for (int s = 1; s < NSPLIT; s++) {
        float v = g_pminv[s][p];
        int id = g_pmini[s][p];
        if (v < bv || (v == bv && id < bi)) { bv = v; bi = id; }
    }

    const int n = p >> 12;
    const int thw = p & 4095;
    const int obase = n * 1048576 + thw;

    float acc = 0.0f;
    #pragma unroll
    for (int q = 0; q < 8; q++) {
        const int d = j * 32 + q * 4;
        float4 wv = *(const float4*)&w[(size_t)bi * DDIM + d];
        float4 zv = *(const float4*)&g_zl[(size_t)p * DDIM + d];
        out[obase + (d + 0) * 4096] = wv.x;
        out[obase + (d + 1) * 4096] = wv.y;
        out[obase + (d + 2) * 4096] = wv.z;
        out[obase + (d + 3) * 4096] = wv.w;
        float dx = wv.x - zv.x, dy = wv.y - zv.y;
        float dz = wv.z - zv.z, dw = wv.w - zv.w;
        acc += dx*dx + dy*dy + dz*dz + dw*dw;
    }
    if (j == 0) out[IDX_OFF + p] = (float)bi;

    lsum[t] = acc;
    __syncthreads();
    #pragma unroll
    for (int s = 128; s > 0; s >>= 1) {
        if (t < s) lsum[t] += lsum[t + s];
        __syncthreads();
    }
    if (t == 0) g_blockloss[blockIdx.x] = lsum[0];
}

// ---------------- Stage D: deterministic loss reduction ----------------
__global__ void vq_loss(float* __restrict__ out) {
    __shared__ float s[256];
    const int t = threadIdx.x;
    s[t] = g_blockloss[t];
    __syncthreads();
    #pragma unroll
    for (int k = 128; k > 0; k >>= 1) {
        if (t < k) s[t] += s[t + k];
        __syncthreads();
    }
    if (t == 0) out[LOSS_OFF] = 1.25f * s[0] / (float)ZQ_ELEMS;
}

// ---------------- launch ----------------
extern "C" void kernel_launch(void* const* d_in, const int* in_sizes, int n_in,
                              void* d_out, int out_size) {
    const float* z = (const float*)d_in[0];
    const float* w = (const float*)d_in[1];
    float* out = (float*)d_out;

    cudaFuncSetAttribute(vq_mma, cudaFuncAttributeMaxDynamicSharedMemorySize, SMEM_TOTAL);

    vq_prep_z<<<8192, 256>>>(z);
    vq_prep_w<<<8192, 256>>>(w);
    vq_wsq<<<1024, 256>>>(w);
    dim3 grid(P_TOTAL / BM, NSPLIT);       // 64 x 2 = 128 CTAs
    vq_mma<<<grid, 256, SMEM_TOTAL>>>();
    vq_gather<<<P_TOTAL / 32, 256>>>(w, out);
    vq_loss<<<1, 256>>>(out);
}

// round 5
// speedup vs baseline: 1.3202x; 1.1182x over previous
#include <cuda_runtime.h>
#include <cstdint>

// ---------------- problem constants ----------------
#define P_TOTAL 8192
#define DDIM    256
#define E_TOTAL 8192
#define NITEMS  2048                   // 64 ptiles * 32 chunks
#define NCTA    148
#define NSLOT   4

#define ZQ_ELEMS 2097152
#define LOSS_OFF 2097152
#define IDX_OFF  2097153

// ---------------- GEMM tiling ----------------
#define BM 128
#define BN 256
#define BK 32
#define TS 36
#define ROWB (TS * 4)                  // 144 B per smem row
#define A_BYTES (BM * ROWB)            // 18432
#define B_BYTES (BN * ROWB)            // 36864
#define AH_OFF 0
#define AL_OFF A_BYTES
#define BH_OFF (2 * A_BYTES)
#define BL_OFF (2 * A_BYTES + B_BYTES)
#define STAGE_BYTES (2 * A_BYTES + 2 * B_BYTES)   // 110592
#define SMEM_TOTAL (2 * STAGE_BYTES)              // 221184

// ---------------- scratch ----------------
__device__ __align__(256) float g_zhi[P_TOTAL * DDIM];   // k-permuted
__device__ __align__(256) float g_zlo[P_TOTAL * DDIM];   // k-permuted
__device__ __align__(256) float g_zl [P_TOTAL * DDIM];   // plain [p][d]
__device__ __align__(256) float g_whi[E_TOTAL * DDIM];   // k-permuted
__device__ __align__(256) float g_wlo[E_TOTAL * DDIM];   // k-permuted
__device__ __align__(256) float g_wsq[E_TOTAL];
__device__ float g_pv[NSLOT][P_TOTAL][16];
__device__ int   g_pi[NSLOT][P_TOTAL][16];
__device__ float g_blockloss[256];

// ---------------- helpers ----------------
__device__ __forceinline__ uint32_t smem_u32(const void* p) {
    uint32_t a;
    asm("{ .reg .u64 t; cvta.to.shared.u64 t, %1; cvt.u32.u64 %0, t; }" : "=r"(a) : "l"(p));
    return a;
}
#define CP16(sa, ga) \
    asm volatile("cp.async.cg.shared.global [%0], [%1], 16;" :: "r"((uint32_t)(sa)), "l"(ga))
#define CP_COMMIT() asm volatile("cp.async.commit_group;" ::: "memory")
#define CP_WAIT0()  asm volatile("cp.async.wait_group 0;" ::: "memory")

__device__ __forceinline__ float tf32r(float x) {
    uint32_t r;
    asm("cvt.rna.tf32.f32 %0, %1;" : "=r"(r) : "f"(x));
    return __uint_as_float(r);
}
__device__ __forceinline__ uint2 lds_u64(uint32_t addr) {
    uint2 v;
    asm volatile("ld.shared.v2.b32 {%0,%1}, [%2];" : "=r"(v.x), "=r"(v.y) : "r"(addr));
    return v;
}
__device__ __forceinline__ void mma_tf32(float& c0, float& c1, float& c2, float& c3,
                                         uint32_t a0, uint32_t a1, uint32_t a2, uint32_t a3,
                                         uint32_t b0, uint32_t b1) {
    asm volatile("mma.sync.aligned.m16n8k8.row.col.f32.tf32.tf32.f32 "
                 "{%0,%1,%2,%3}, {%4,%5,%6,%7}, {%8,%9}, {%0,%1,%2,%3};"
                 : "+f"(c0), "+f"(c1), "+f"(c2), "+f"(c3)
                 : "r"(a0), "r"(a1), "r"(a2), "r"(a3), "r"(b0), "r"(b1));
}
__device__ __forceinline__ int dperm(int d) {
    return ((d >> 3) << 3) + ((d & 3) << 1) + ((d >> 2) & 1);
}

// ---------------- Stage A1: z -> (z_hi, z_lo) permuted + plain + partial init ----
__global__ void vq_prep_z(const float* __restrict__ z) {
    int idx = blockIdx.x * 256 + threadIdx.x;
    float v = z[idx];
    int n = idx >> 20, rem = idx & 1048575;
    int d = rem >> 12, thw = rem & 4095;
    int p = (n << 12) + thw;
    float hi = tf32r(v);
    int op = p * DDIM + dperm(d);
    g_zhi[op] = hi;
    g_zlo[op] = tf32r(v - hi);
    g_zl[p * DDIM + d] = v;
    if (idx < NSLOT * P_TOTAL * 16) {
        ((float*)g_pv)[idx] = __int_as_float(0x7f800000);
        ((int*)g_pi)[idx] = 0;
    }
}

// ---------------- Stage A2: w -> (w_hi, w_lo) permuted ----------------
__global__ void vq_prep_w(const float* __restrict__ w) {
    int idx = blockIdx.x * 256 + threadIdx.x;
    float v = w[idx];
    int e = idx >> 8, d = idx & 255;
    float hi = tf32r(v);
    int op = e * DDIM + dperm(d);
    g_whi[op] = hi;
    g_wlo[op] = tf32r(v - hi);
}

// ---------------- Stage A3: ||w_e||^2 ----------------
__global__ void vq_wsq(const float* __restrict__ w) {
    int gwarp = (blockIdx.x * blockDim.x + threadIdx.x) >> 5;
    int lane = threadIdx.x & 31;
    const float* row = w + (size_t)gwarp * DDIM;
    float4 a = *(const float4*)&row[lane * 4];
    float4 b = *(const float4*)&row[128 + lane * 4];
    float s = a.x*a.x + a.y*a.y + a.z*a.z + a.w*a.w
            + b.x*b.x + b.y*b.y + b.z*b.z + b.w*b.w;
    #pragma unroll
    for (int off = 16; off >= 1; off >>= 1)
        s += __shfl_down_sync(0xffffffffu, s, off);
    if (lane == 0) g_wsq[gwarp] = s;
}

// ---------------- Stage B: persistent fused 3xTF32 distance GEMM + argmin ------
__global__ __launch_bounds__(256, 1)
void vq_mma() {
    extern __shared__ float sm[];
    const uint32_t sb = smem_u32(sm);

    const int t = threadIdx.x;
    const int lane = t & 31, wid = t >> 5;
    const int warpM = wid >> 2;          // 0..1
    const int warpN = wid & 3;           // 0..3
    const int g = lane >> 2;             // 0..7
    const int tg = lane & 3;             // 0..3
    const int bid = blockIdx.x;
    const int slot = bid & 3;
    const uint32_t koff_tg = tg * 8;

    // exact-tiling work ranges: [bid*NITEMS/NCTA, (bid+1)*NITEMS/NCTA)
    const int itlo = (bid * NITEMS) / NCTA;
    const int ithi = ((bid + 1) * NITEMS) / NCTA;
    const int nsteps = (ithi - itlo) * 8;

    // loader per-thread constants
    const int lr0 = t >> 3;              // 0..31
    const int lqc = t & 7;               // 0..7
    const uint32_t sm_a = (uint32_t)(lr0 * ROWB + lqc * 16);

    float bestv[4][2];
    int   besti[4][2];
    #pragma unroll
    for (int mi = 0; mi < 4; mi++)
        #pragma unroll
        for (int h = 0; h < 2; h++) { bestv[mi][h] = __int_as_float(0x7f800000); besti[mi][h] = 0; }

    float acc[4][8][4];

    auto issue_load = [&](int L) {
        const int item = itlo + (L >> 3);
        const int k0 = (L & 7) << 5;
        const size_t abase = ((size_t)((item >> 5) * BM + lr0)) * DDIM + lqc * 4 + k0;
        const size_t bbase = ((size_t)((item & 31) * BN + lr0)) * DDIM + lqc * 4 + k0;
        const uint32_t base = sb + (uint32_t)(L & 1) * STAGE_BYTES + sm_a;
        #pragma unroll
        for (int i = 0; i < 4; i++)
            CP16(base + AH_OFF + i * 32 * ROWB, g_zhi + abase + (size_t)i * 32 * DDIM);
        #pragma unroll
        for (int i = 0; i < 4; i++)
            CP16(base + AL_OFF + i * 32 * ROWB, g_zlo + abase + (size_t)i * 32 * DDIM);
        #pragma unroll
        for (int i = 0; i < 8; i++)
            CP16(base + BH_OFF + i * 32 * ROWB, g_whi + bbase + (size_t)i * 32 * DDIM);
        #pragma unroll
        for (int i = 0; i < 8; i++)
            CP16(base + BL_OFF + i * 32 * ROWB, g_wlo + bbase + (size_t)i * 32 * DDIM);
        CP_COMMIT();
    };

    issue_load(0);

    #pragma unroll 1
    for (int S = 0; S < nsteps; S++) {
        CP_WAIT0();
        __syncthreads();
        if (S + 1 < nsteps) issue_load(S + 1);

        const int s8 = S & 7;
        if (s8 == 0) {
            #pragma unroll
            for (int mi = 0; mi < 4; mi++)
                #pragma unroll
                for (int ni = 0; ni < 8; ni++)
                    #pragma unroll
                    for (int q = 0; q < 4; q++) acc[mi][ni][q] = 0.0f;
        }

        const uint32_t base = sb + (uint32_t)(S & 1) * STAGE_BYTES;

        #pragma unroll
        for (int k8 = 0; k8 < 4; k8++) {
            const uint32_t ko = k8 * 32 + koff_tg;
            uint2 bh[8], bl[8];
            #pragma unroll
            for (int ni = 0; ni < 8; ni++) {
                const uint32_t rb = (uint32_t)((warpN * 64 + ni * 8 + g) * ROWB) + ko;
                bh[ni] = lds_u64(base + BH_OFF + rb);
                bl[ni] = lds_u64(base + BL_OFF + rb);
            }
            uint2 ahA[4], ahB[4], alA[4], alB[4];
            #pragma unroll
            for (int mi = 0; mi < 4; mi++) {
                const uint32_t ra = (uint32_t)((warpM * 64 + mi * 16 + g) * ROWB) + ko;
                ahA[mi] = lds_u64(base + AH_OFF + ra);
                ahB[mi] = lds_u64(base + AH_OFF + ra + 8 * ROWB);
                alA[mi] = lds_u64(base + AL_OFF + ra);
                alB[mi] = lds_u64(base + AL_OFF + ra + 8 * ROWB);
            }
            // product 1: Zh x Wh
            #pragma unroll
            for (int mi = 0; mi < 4; mi++)
                #pragma unroll
                for (int ni = 0; ni < 8; ni++)
                    mma_tf32(acc[mi][ni][0], acc[mi][ni][1], acc[mi][ni][2], acc[mi][ni][3],
                             ahA[mi].x, ahB[mi].x, ahA[mi].y, ahB[mi].y, bh[ni].x, bh[ni].y);
            // product 2: Zl x Wh
            #pragma unroll
            for (int mi = 0; mi < 4; mi++)
                #pragma unroll
                for (int ni = 0; ni < 8; ni++)
                    mma_tf32(acc[mi][ni][0], acc[mi][ni][1], acc[mi][ni][2], acc[mi][ni][3],
                             alA[mi].x, alB[mi].x, alA[mi].y, alB[mi].y, bh[ni].x, bh[ni].y);
            // product 3: Zh x Wl
            #pragma unroll
            for (int mi = 0; mi < 4; mi++)
                #pragma unroll
                for (int ni = 0; ni < 8; ni++)
                    mma_tf32(acc[mi][ni][0], acc[mi][ni][1], acc[mi][ni][2], acc[mi][ni][3],
                             ahA[mi].x, ahB[mi].x, ahA[mi].y, ahB[mi].y, bl[ni].x, bl[ni].y);
        }

        if (s8 == 7) {
            const int item = itlo + (S >> 3);
            const int e0 = (item & 31) * BN;
            // running argmin update
            #pragma unroll
            for (int ni = 0; ni < 8; ni++) {
                const int cl = warpN * 64 + ni * 8 + tg * 2;
                const float2 wq = *(const float2*)&g_wsq[e0 + cl];
                #pragma unroll
                for (int mi = 0; mi < 4; mi++) {
                    #pragma unroll
                    for (int h = 0; h < 2; h++) {
                        float d0 = wq.x - 2.0f * acc[mi][ni][h * 2 + 0];
                        float d1 = wq.y - 2.0f * acc[mi][ni][h * 2 + 1];
                        if (d0 < bestv[mi][h]) { bestv[mi][h] = d0; besti[mi][h] = e0 + cl; }
                        if (d1 < bestv[mi][h]) { bestv[mi][h] = d1; besti[mi][h] = e0 + cl + 1; }
                    }
                }
            }
            // flush if this was the last chunk for this ptile
            const bool last = (S + 1 == nsteps) ||
                              ((itlo + ((S + 1) >> 3)) >> 5) != (item >> 5);
            if (last) {
                const int p0 = (item >> 5) * BM;
                const int c = warpN * 4 + tg;
                #pragma unroll
                for (int mi = 0; mi < 4; mi++)
                    #pragma unroll
                    for (int h = 0; h < 2; h++) {
                        int p = p0 + warpM * 64 + mi * 16 + h * 8 + g;
                        g_pv[slot][p][c] = bestv[mi][h];
                        g_pi[slot][p][c] = besti[mi][h];
                        bestv[mi][h] = __int_as_float(0x7f800000);
                        besti[mi][h] = 0;
                    }
            }
        }
    }
}

// ---------------- Stage C: combine partials, gather z_q, loss partials ----------
__global__ void vq_gather(const float* __restrict__ w, float* __restrict__ out) {
    __shared__ float lsum[256];
    const int t = threadIdx.x;
    const int p = blockIdx.x * 32 + (t >> 3);
    const int j = t & 7;

    // reduce 64 (slot, col) candidates: 8 per thread, then shfl over 8 threads
    float bv = __int_as_float(0x7f800000);
    int bi = 0;
    #pragma unroll
    for (int q = 0; q < 8; q++) {
        int f = j * 8 + q;
        float v = g_pv[f >> 4][p][f & 15];
        int   i = g_pi[f >> 4][p][f & 15];
        if (v < bv || (v == bv && i < bi)) { bv = v; bi = i; }
    }
    #pragma unroll
    for (int off = 4; off >= 1; off >>= 1) {
        float ov = __shfl_down_sync(0xffffffffu, bv, off, 8);
        int   oi = __shfl_down_sync(0xffffffffu, bi, off, 8);
        if (ov < bv || (ov == bv && oi < bi)) { bv = ov; bi = oi; }
    }
    bi = __shfl_sync(0xffffffffu, bi, (t & 31) & ~7);

    const int n = p >> 12;
    const int thw = p & 4095;
    const int obase = n * 1048576 + thw;

    float acc = 0.0f;
    #pragma unroll
    for (int q = 0; q < 8; q++) {
        const int d = j * 32 + q * 4;
        float4 wv = *(const float4*)&w[(size_t)bi * DDIM + d];
        float4 zv = *(const float4*)&g_zl[(size_t)p * DDIM + d];
        out[obase + (d + 0) * 4096] = wv.x;
        out[obase + (d + 1) * 4096] = wv.y;
        out[obase + (d + 2) * 4096] = wv.z;
        out[obase + (d + 3) * 4096] = wv.w;
        float dx = wv.x - zv.x, dy = wv.y - zv.y;
        float dz = wv.z - zv.z, dw = wv.w - zv.w;
        acc += dx*dx + dy*dy + dz*dz + dw*dw;
    }
    if (j == 0) out[IDX_OFF + p] = (float)bi;

    lsum[t] = acc;
    __syncthreads();
    #pragma unroll
    for (int s = 128; s > 0; s >>= 1) {
        if (t < s) lsum[t] += lsum[t + s];
        __syncthreads();
    }
    if (t == 0) g_blockloss[blockIdx.x] = lsum[0];
}

// ---------------- Stage D: deterministic loss reduction ----------------
__global__ void vq_loss(float* __restrict__ out) {
    __shared__ float s[256];
    const int t = threadIdx.x;
    s[t] = g_blockloss[t];
    __syncthreads();
    #pragma unroll
    for (int k = 128; k > 0; k >>= 1) {
        if (t < k) s[t] += s[t + k];
        __syncthreads();
    }
    if (t == 0) out[LOSS_OFF] = 1.25f * s[0] / (float)ZQ_ELEMS;
}

// ---------------- launch ----------------
extern "C" void kernel_launch(void* const* d_in, const int* in_sizes, int n_in,
                              void* d_out, int out_size) {
    const float* z = (const float*)d_in[0];
    const float* w = (const float*)d_in[1];
    float* out = (float*)d_out;

    cudaFuncSetAttribute(vq_mma, cudaFuncAttributeMaxDynamicSharedMemorySize, SMEM_TOTAL);

    vq_prep_z<<<8192, 256>>>(z);
    vq_prep_w<<<8192, 256>>>(w);
    vq_wsq<<<1024, 256>>>(w);
    vq_mma<<<NCTA, 256, SMEM_TOTAL>>>();
    vq_gather<<<P_TOTAL / 32, 256>>>(w, out);
    vq_loss<<<1, 256>>>(out);
}

// round 7
// speedup vs baseline: 1.3493x; 1.0220x over previous
#include <cuda_runtime.h>
#include <cstdint>

// ---------------- problem constants ----------------
#define P_TOTAL 8192
#define DDIM    256
#define E_TOTAL 8192
#define NITEMS  2048                   // 64 ptiles * 32 chunks
#define NCTA    148
#define NSLOT   4

#define ZQ_ELEMS 2097152
#define LOSS_OFF 2097152
#define IDX_OFF  2097153

// ---------------- GEMM tiling ----------------
#define BM 128
#define BN 256
#define BK 32
#define TS 36
#define ROWB (TS * 4)                  // 144 B per smem row
#define A_BYTES (BM * ROWB)            // 18432
#define B_BYTES (BN * ROWB)            // 36864
#define AH_OFF 0
#define AL_OFF A_BYTES
#define BH_OFF (2 * A_BYTES)
#define BL_OFF (2 * A_BYTES + B_BYTES)
#define STAGE_BYTES (2 * A_BYTES + 2 * B_BYTES)   // 110592
#define SMEM_TOTAL (2 * STAGE_BYTES)              // 221184

// ---------------- scratch ----------------
__device__ __align__(256) float g_zhi[P_TOTAL * DDIM];   // k-permuted
__device__ __align__(256) float g_zlo[P_TOTAL * DDIM];   // k-permuted
__device__ __align__(256) float g_zl [P_TOTAL * DDIM];   // plain [p][d]
__device__ __align__(256) float g_whi[E_TOTAL * DDIM];   // k-permuted
__device__ __align__(256) float g_wlo[E_TOTAL * DDIM];   // k-permuted
__device__ __align__(256) float g_wsq[E_TOTAL];
__device__ float g_pv[NSLOT][P_TOTAL][16];
__device__ int   g_pi[NSLOT][P_TOTAL][16];
__device__ float g_blockloss[256];

// ---------------- helpers ----------------
__device__ __forceinline__ uint32_t smem_u32(const void* p) {
    uint32_t a;
    asm("{ .reg .u64 t; cvta.to.shared.u64 t, %1; cvt.u32.u64 %0, t; }" : "=r"(a) : "l"(p));
    return a;
}
#define CP16(sa, ga) \
    asm volatile("cp.async.cg.shared.global [%0], [%1], 16;" :: "r"((uint32_t)(sa)), "l"(ga))
#define CP_COMMIT() asm volatile("cp.async.commit_group;" ::: "memory")
#define CP_WAIT0()  asm volatile("cp.async.wait_group 0;" ::: "memory")

__device__ __forceinline__ float tf32r(float x) {
    uint32_t r;
    asm("cvt.rna.tf32.f32 %0, %1;" : "=r"(r) : "f"(x));
    return __uint_as_float(r);
}
__device__ __forceinline__ uint2 lds_u64(uint32_t addr) {
    uint2 v;
    asm volatile("ld.shared.v2.b32 {%0,%1}, [%2];" : "=r"(v.x), "=r"(v.y) : "r"(addr));
    return v;
}
__device__ __forceinline__ void mma_tf32(float& c0, float& c1, float& c2, float& c3,
                                         uint32_t a0, uint32_t a1, uint32_t a2, uint32_t a3,
                                         uint32_t b0, uint32_t b1) {
    asm volatile("mma.sync.aligned.m16n8k8.row.col.f32.tf32.tf32.f32 "
                 "{%0,%1,%2,%3}, {%4,%5,%6,%7}, {%8,%9}, {%0,%1,%2,%3};"
                 : "+f"(c0), "+f"(c1), "+f"(c2), "+f"(c3)
                 : "r"(a0), "r"(a1), "r"(a2), "r"(a3), "r"(b0), "r"(b1));
}
__device__ __forceinline__ int dperm(int d) {
    return ((d >> 3) << 3) + ((d & 3) << 1) + ((d >> 2) & 1);
}

// ---------------- Stage A1: z -> (z_hi, z_lo) permuted + plain + partial init ----
__global__ void vq_prep_z(const float* __restrict__ z) {
    int idx = blockIdx.x * 256 + threadIdx.x;
    float v = z[idx];
    int n = idx >> 20, rem = idx & 1048575;
    int d = rem >> 12, thw = rem & 4095;
    int p = (n << 12) + thw;
    float hi = tf32r(v);
    int op = p * DDIM + dperm(d);
    g_zhi[op] = hi;
    g_zlo[op] = tf32r(v - hi);
    g_zl[p * DDIM + d] = v;
    if (idx < NSLOT * P_TOTAL * 16) {
        ((float*)g_pv)[idx] = __int_as_float(0x7f800000);
        ((int*)g_pi)[idx] = 0;
    }
}

// ---------------- Stage A2: w -> (w_hi, w_lo) permuted ----------------
__global__ void vq_prep_w(const float* __restrict__ w) {
    int idx = blockIdx.x * 256 + threadIdx.x;
    float v = w[idx];
    int e = idx >> 8, d = idx & 255;
    float hi = tf32r(v);
    int op = e * DDIM + dperm(d);
    g_whi[op] = hi;
    g_wlo[op] = tf32r(v - hi);
}

// ---------------- Stage A3: ||w_e||^2 ----------------
__global__ void vq_wsq(const float* __restrict__ w) {
    int gwarp = (blockIdx.x * blockDim.x + threadIdx.x) >> 5;
    int lane = threadIdx.x & 31;
    const float* row = w + (size_t)gwarp * DDIM;
    float4 a = *(const float4*)&row[lane * 4];
    float4 b = *(const float4*)&row[128 + lane * 4];
    float s = a.x*a.x + a.y*a.y + a.z*a.z + a.w*a.w
            + b.x*b.x + b.y*b.y + b.z*b.z + b.w*b.w;
    #pragma unroll
    for (int off = 16; off >= 1; off >>= 1)
        s += __shfl_down_sync(0xffffffffu, s, off);
    if (lane == 0) g_wsq[gwarp] = s;
}

// ---------------- Stage B: persistent fused 3xTF32 distance GEMM + argmin ------
__global__ __launch_bounds__(256, 1)
void vq_mma() {
    extern __shared__ float sm[];
    const uint32_t sb = smem_u32(sm);

    const int t = threadIdx.x;
    const int lane = t & 31, wid = t >> 5;
    const int warpM = wid >> 2;          // 0..1
    const int warpN = wid & 3;           // 0..3
    const int g = lane >> 2;             // 0..7
    const int tg = lane & 3;             // 0..3
    const int bid = blockIdx.x;
    const int slot = bid & 3;
    const uint32_t koff_tg = tg * 8;

    // exact-tiling work ranges
    const int itlo = (bid * NITEMS) / NCTA;
    const int ithi = ((bid + 1) * NITEMS) / NCTA;
    const int nsteps = (ithi - itlo) * 8;

    // loader per-thread constants
    const int lr0 = t >> 3;              // 0..31
    const int lqc = t & 7;               // 0..7
    const uint32_t sm_a = (uint32_t)(lr0 * ROWB + lqc * 16);
    const size_t toff = (size_t)lr0 * DDIM + lqc * 4;

    // ---- incremental loader state (prefetch cursor) ----
    const float* pAh = g_zhi + (size_t)(itlo >> 5) * BM * DDIM + toff;
    const float* pAl = g_zlo + (size_t)(itlo >> 5) * BM * DDIM + toff;
    const float* pBh = g_whi + (size_t)(itlo & 31) * BN * DDIM + toff;
    const float* pBl = g_wlo + (size_t)(itlo & 31) * BN * DDIM + toff;
    int nextk = 0;                        // float offset within row (0,32,...,224)
    int nchunk = itlo & 31;
    uint32_t lstage = sb + sm_a;          // toggles between the two stages
    int lsgn = STAGE_BYTES;               // add-toggle (XOR is wrong: unaligned base)

    auto issue_load = [&]() {
        const float* ah = pAh + nextk;
        const float* al = pAl + nextk;
        const float* bh = pBh + nextk;
        const float* bl = pBl + nextk;
        const uint32_t base = lstage;
        #pragma unroll
        for (int i = 0; i < 4; i++)
            CP16(base + AH_OFF + i * 32 * ROWB, ah + (size_t)i * 32 * DDIM);
        #pragma unroll
        for (int i = 0; i < 4; i++)
            CP16(base + AL_OFF + i * 32 * ROWB, al + (size_t)i * 32 * DDIM);
        #pragma unroll
        for (int i = 0; i < 8; i++)
            CP16(base + BH_OFF + i * 32 * ROWB, bh + (size_t)i * 32 * DDIM);
        #pragma unroll
        for (int i = 0; i < 8; i++)
            CP16(base + BL_OFF + i * 32 * ROWB, bl + (size_t)i * 32 * DDIM);
        CP_COMMIT();
        // advance cursor
        lstage += lsgn; lsgn = -lsgn;
        nextk += 32;
        if (nextk == 256) {
            nextk = 0;
            pBh += (size_t)BN * DDIM;
            pBl += (size_t)BN * DDIM;
            if (++nchunk == 32) {
                nchunk = 0;
                pBh -= (size_t)E_TOTAL * DDIM;
                pBl -= (size_t)E_TOTAL * DDIM;
                pAh += (size_t)BM * DDIM;
                pAl += (size_t)BM * DDIM;
            }
        }
    };

    float bestv[4][2];
    int   besti[4][2];
    #pragma unroll
    for (int mi = 0; mi < 4; mi++)
        #pragma unroll
        for (int h = 0; h < 2; h++) { bestv[mi][h] = __int_as_float(0x7f800000); besti[mi][h] = 0; }

    float acc[4][8][4];

    issue_load();

    uint32_t cstage = sb;                 // compute-side stage base
    int csgn = STAGE_BYTES;

    #pragma unroll 1
    for (int S = 0; S < nsteps; S++) {
        CP_WAIT0();
        __syncthreads();
        if (S + 1 < nsteps) issue_load();

        const int s8 = S & 7;
        if (s8 == 0) {
            #pragma unroll
            for (int mi = 0; mi < 4; mi++)
                #pragma unroll
                for (int ni = 0; ni < 8; ni++)
                    #pragma unroll
                    for (int q = 0; q < 4; q++) acc[mi][ni][q] = 0.0f;
        }

        const uint32_t base = cstage;
        cstage += csgn; csgn = -csgn;

        #pragma unroll
        for (int k8 = 0; k8 < 4; k8++) {
            const uint32_t ko = k8 * 32 + koff_tg;
            uint2 bh[8], bl[8];
            #pragma unroll
            for (int ni = 0; ni < 8; ni++) {
                const uint32_t rb = (uint32_t)((warpN * 64 + ni * 8 + g) * ROWB) + ko;
                bh[ni] = lds_u64(base + BH_OFF + rb);
                bl[ni] = lds_u64(base + BL_OFF + rb);
            }
            uint2 ahA[4], ahB[4], alA[4], alB[4];
            #pragma unroll
            for (int mi = 0; mi < 4; mi++) {
                const uint32_t ra = (uint32_t)((warpM * 64 + mi * 16 + g) * ROWB) + ko;
                ahA[mi] = lds_u64(base + AH_OFF + ra);
                ahB[mi] = lds_u64(base + AH_OFF + ra + 8 * ROWB);
                alA[mi] = lds_u64(base + AL_OFF + ra);
                alB[mi] = lds_u64(base + AL_OFF + ra + 8 * ROWB);
            }
            // product 1: Zh x Wh
            #pragma unroll
            for (int mi = 0; mi < 4; mi++)
                #pragma unroll
                for (int ni = 0; ni < 8; ni++)
                    mma_tf32(acc[mi][ni][0], acc[mi][ni][1], acc[mi][ni][2], acc[mi][ni][3],
                             ahA[mi].x, ahB[mi].x, ahA[mi].y, ahB[mi].y, bh[ni].x, bh[ni].y);
            // product 2: Zl x Wh
            #pragma unroll
            for (int mi = 0; mi < 4; mi++)
                #pragma unroll
                for (int ni = 0; ni < 8; ni++)
                    mma_tf32(acc[mi][ni][0], acc[mi][ni][1], acc[mi][ni][2], acc[mi][ni][3],
                             alA[mi].x, alB[mi].x, alA[mi].y, alB[mi].y, bh[ni].x, bh[ni].y);
            // product 3: Zh x Wl
            #pragma unroll
            for (int mi = 0; mi < 4; mi++)
                #pragma unroll
                for (int ni = 0; ni < 8; ni++)
                    mma_tf32(acc[mi][ni][0], acc[mi][ni][1], acc[mi][ni][2], acc[mi][ni][3],
                             ahA[mi].x, ahB[mi].x, ahA[mi].y, ahB[mi].y, bl[ni].x, bl[ni].y);
        }

        if (s8 == 7) {
            const int item = itlo + (S >> 3);
            const int e0 = (item & 31) * BN;
            #pragma unroll
            for (int ni = 0; ni < 8; ni++) {
                const int cl = warpN * 64 + ni * 8 + tg * 2;
                const float2 wq = *(const float2*)&g_wsq[e0 + cl];
                #pragma unroll
                for (int mi = 0; mi < 4; mi++) {
                    #pragma unroll
                    for (int h = 0; h < 2; h++) {
                        float d0 = wq.x - 2.0f * acc[mi][ni][h * 2 + 0];
                        float d1 = wq.y - 2.0f * acc[mi][ni][h * 2 + 1];
                        if (d0 < bestv[mi][h]) { bestv[mi][h] = d0; besti[mi][h] = e0 + cl; }
                        if (d1 < bestv[mi][h]) { bestv[mi][h] = d1; besti[mi][h] = e0 + cl + 1; }
                    }
                }
            }
            const bool last = (S + 1 == nsteps) ||
                              ((itlo + ((S + 1) >> 3)) >> 5) != (item >> 5);
            if (last) {
                const int p0 = (item >> 5) * BM;
                const int c = warpN * 4 + tg;
                #pragma unroll
                for (int mi = 0; mi < 4; mi++)
                    #pragma unroll
                    for (int h = 0; h < 2; h++) {
                        int p = p0 + warpM * 64 + mi * 16 + h * 8 + g;
                        g_pv[slot][p][c] = bestv[mi][h];
                        g_pi[slot][p][c] = besti[mi][h];
                        bestv[mi][h] = __int_as_float(0x7f800000);
                        besti[mi][h] = 0;
                    }
            }
        }
    }
}

// ---------------- Stage C: combine partials, gather z_q, loss partials ----------
__global__ void vq_gather(const float* __restrict__ w, float* __restrict__ out) {
    __shared__ float lsum[256];
    const int t = threadIdx.x;
    const int p = blockIdx.x * 32 + (t >> 3);
    const int j = t & 7;

    float bv = __int_as_float(0x7f800000);
    int bi = 0;
    #pragma unroll
    for (int q = 0; q < 8; q++) {
        int f = j * 8 + q;
        float v = g_pv[f >> 4][p][f & 15];
        int   i = g_pi[f >> 4][p][f & 15];
        if (v < bv || (v == bv && i < bi)) { bv = v; bi = i; }
    }
    #pragma unroll
    for (int off = 4; off >= 1; off >>= 1) {
        float ov = __shfl_down_sync(0xffffffffu, bv, off, 8);
        int   oi = __shfl_down_sync(0xffffffffu, bi, off, 8);
        if (ov < bv || (ov == bv && oi < bi)) { bv = ov; bi = oi; }
    }
    bi = __shfl_sync(0xffffffffu, bi, (t & 31) & ~7);

    const int n = p >> 12;
    const int thw = p & 4095;
    const int obase = n * 1048576 + thw;

    float acc = 0.0f;
    #pragma unroll
    for (int q = 0; q < 8; q++) {
        const int d = j * 32 + q * 4;
        float4 wv = *(const float4*)&w[(size_t)bi * DDIM + d];
        float4 zv = *(const float4*)&g_zl[(size_t)p * DDIM + d];
        out[obase + (d + 0) * 4096] = wv.x;
        out[obase + (d + 1) * 4096] = wv.y;
        out[obase + (d + 2) * 4096] = wv.z;
        out[obase + (d + 3) * 4096] = wv.w;
        float dx = wv.x - zv.x, dy = wv.y - zv.y;
        float dz = wv.z - zv.z, dw = wv.w - zv.w;
        acc += dx*dx + dy*dy + dz*dz + dw*dw;
    }
    if (j == 0) out[IDX_OFF + p] = (float)bi;

    lsum[t] = acc;
    __syncthreads();
    #pragma unroll
    for (int s = 128; s > 0; s >>= 1) {
        if (t < s) lsum[t] += lsum[t + s];
        __syncthreads();
    }
    if (t == 0) g_blockloss[blockIdx.x] = lsum[0];
}

// ---------------- Stage D: deterministic loss reduction ----------------
__global__ void vq_loss(float* __restrict__ out) {
    __shared__ float s[256];
    const int t = threadIdx.x;
    s[t] = g_blockloss[t];
    __syncthreads();
    #pragma unroll
    for (int k = 128; k > 0; k >>= 1) {
        if (t < k) s[t] += s[t + k];
        __syncthreads();
    }
    if (t == 0) out[LOSS_OFF] = 1.25f * s[0] / (float)ZQ_ELEMS;
}

// ---------------- launch ----------------
extern "C" void kernel_launch(void* const* d_in, const int* in_sizes, int n_in,
                              void* d_out, int out_size) {
    const float* z = (const float*)d_in[0];
    const float* w = (const float*)d_in[1];
    float* out = (float*)d_out;

    cudaFuncSetAttribute(vq_mma, cudaFuncAttributeMaxDynamicSharedMemorySize, SMEM_TOTAL);

    vq_prep_z<<<8192, 256>>>(z);
    vq_prep_w<<<8192, 256>>>(w);
    vq_wsq<<<1024, 256>>>(w);
    vq_mma<<<NCTA, 256, SMEM_TOTAL>>>();
    vq_gather<<<P_TOTAL / 32, 256>>>(w, out);
    vq_loss<<<1, 256>>>(out);
}